// round 13
// baseline (speedup 1.0000x reference)
#include <cuda_runtime.h>
#include <cuda_fp16.h>

// Problem constants
#define M_OUT   125000
#define KNB     8
#define CIN     96
#define COUT    192
#define BM      64
#define NCHUNK  12                        // K chunks of 64 (768 total)
#define NBLK    1954                      // ceil(125000/64)
#define NBLKP   1956                      // padded to /4 for vectorized stats
#define BN_EPS  1e-5f
#define SA      36                        // smem row stride in words (conflict-free)

// Dynamic smem word offsets: A double-buffered, B double-buffered.
#define NW_A    (BM * SA)                 // 2304
#define NW_B    (COUT * SA)               // 6912
#define O_A(s)    ((s) * NW_A)                    // 0 .. 4608
#define O_B(s)    (4608 + (s) * NW_B)             // .. 18432
#define O_SROW    18432                           // 512 words
#define POOLW     18944
#define POOLB     (POOLW * 4)                     // 75776 B -> 2 CTAs/SM

// Deterministic scratch
__device__ float g_psum[COUT * NBLKP];
__device__ float g_psq [COUT * NBLKP];
__device__ __align__(16) float g_scale[COUT];
__device__ __align__(16) float g_shift[COUT];
__device__ int   g_is64;
__device__ unsigned g_ctr;                 // last-block-done counter
// Pre-packed fp16 weights: [t][n][w] word = half2 over (k,k+1), k = 64t + 2w
__device__ __align__(16) unsigned g_wf[NCHUNK * COUT * 32];

#define HMMA(d, a0, a1, a2, a3, b0, b1)                                        \
    asm volatile(                                                              \
        "mma.sync.aligned.m16n8k16.row.col.f32.f16.f16.f32 "                   \
        "{%0,%1,%2,%3}, {%4,%5,%6,%7}, {%8,%9}, {%0,%1,%2,%3};"                \
        : "+f"((d)[0]), "+f"((d)[1]), "+f"((d)[2]), "+f"((d)[3])               \
        : "r"(a0), "r"(a1), "r"(a2), "r"(a3), "r"(b0), "r"(b1))

#define LDSM4(r0, r1, r2, r3, addr)                                            \
    asm volatile("ldmatrix.sync.aligned.m8n8.x4.shared.b16 {%0,%1,%2,%3}, [%4];" \
        : "=r"(r0), "=r"(r1), "=r"(r2), "=r"(r3) : "r"(addr))

#define CP_ASYNC16(dst_u32, src_ptr)                                           \
    asm volatile("cp.async.ca.shared.global [%0], [%1], 16;"                   \
        :: "r"(dst_u32), "l"(src_ptr))
#define CP_COMMIT()  asm volatile("cp.async.commit_group;" ::: "memory")
#define CP_WAIT0()   asm volatile("cp.async.wait_group 0;" ::: "memory")

// ---------------------------------------------------------------------------
// Fused prepack (blocks 0..11) + detect / pad-zero / counter reset (block 12).
// ---------------------------------------------------------------------------
__global__ __launch_bounds__(256) void prep_kernel(const float* __restrict__ W,
                                                   const int* __restrict__ neigh32)
{
    const int t = blockIdx.x;
    if (t < NCHUNK) {
        for (int idx = threadIdx.x; idx < COUT * 32; idx += 256) {
            int n = idx >> 5, w = idx & 31;
            int k0 = t * 64 + 2 * w;
            __half2 h = __floats2half2_rn(W[k0 * COUT + n], W[(k0 + 1) * COUT + n]);
            g_wf[t * 6144 + n * 32 + w] = *reinterpret_cast<unsigned*>(&h);
        }
    } else {
        for (int idx = threadIdx.x; idx < COUT * 2; idx += 256) {
            int c = idx >> 1, p = idx & 1;
            g_psum[c * NBLKP + NBLK + p] = 0.0f;
            g_psq [c * NBLKP + NBLK + p] = 0.0f;
        }
        if (threadIdx.x == 0) {
            g_ctr = 0u;                    // reset for every graph replay
            int is64 = 1;
            for (int i = 0; i < 256; ++i)
                if (neigh32[2 * i + 1] != 0) { is64 = 0; break; }
            g_is64 = is64;
        }
    }
}

// ---------------------------------------------------------------------------
// Conv kernel: gather-GEMM on fp16 tensor cores + fused BN stats finalization
// by the last CTA (last-block-done pattern).
// Block = 64 rows x 192 cols, 8 warps as 2(M) x 4(N); warp tile 32x48.
// ---------------------------------------------------------------------------
__global__ __launch_bounds__(256, 2) void conv_kernel(
    const float* __restrict__ data,
    const float* __restrict__ bias,
    const float* __restrict__ gamma,
    const float* __restrict__ beta,
    const void* __restrict__ neigh_raw,
    float* __restrict__ out)
{
    extern __shared__ __align__(16) unsigned pool[];
    int*   sSrow = (int*)&pool[O_SROW];
    float* RedS  = (float*)pool;              // overlay after MMA: [2][192]
    float* RedQ  = RedS + 2 * COUT;
    unsigned* sFlag = (unsigned*)(RedQ + 2 * COUT);

    const int tid = threadIdx.x;
    const int lid = tid & 31;
    const int wid = tid >> 5;                 // 0..7
    const int wm  = wid & 1;                  // 0..1 (M): rows wm*32..+31
    const int wn  = wid >> 1;                 // 0..3 (N): cols wn*48..+47
    const int gid = lid >> 2;                 // 0..7
    const int tig = lid & 3;                  // 0..3
    const int bx  = blockIdx.x;
    const int m0  = bx * BM;

    const int is64 = g_is64;
    const long long* n64 = (const long long*)neigh_raw;
    const int*       n32 = (const int*)neigh_raw;

    // Stage neighbor indices [64][8]
    for (int idx = tid; idx < BM * KNB; idx += 256) {
        int r  = idx >> 3;
        int kk = idx & 7;
        int m  = m0 + r;
        int srow = -1;
        if (m < M_OUT) {
            long long v = is64 ? n64[(long long)m * KNB + kk]
                               : (long long)n32[(long long)m * KNB + kk];
            if (v >= 0) srow = (int)v;
        }
        sSrow[idx] = srow;
    }
    __syncthreads();

    // ldmatrix lane-static addresses (byte offsets into pool)
    const unsigned sbase = (unsigned)__cvta_generic_to_shared(pool);
    const unsigned aLane = sbase +
        (((wm * 32 + (lid & 15)) * SA + ((lid & 16) ? 4u : 0u)) << 2);
    const unsigned bLane = sbase + ((O_B(0) +
        ((wn * 48 + ((lid >> 4) & 1) * 8 + (lid & 7)) * SA +
         ((lid & 8) ? 4u : 0u))) << 2);

    // Gather staging: 1024 float4 items -> 4 per thread. item -> (row, g)
    float4 fst[4];

#define GATHER(T)                                                              \
    _Pragma("unroll")                                                          \
    for (int i = 0; i < 4; ++i) {                                              \
        int idx = tid + 256 * i;                                               \
        int r = idx >> 4, g = idx & 15;                                        \
        int k0 = ((T) << 6) + (g << 2);                                        \
        int kk = k0 / 96, c = k0 - 96 * kk;                                    \
        int srow = sSrow[r * KNB + kk];                                        \
        fst[i] = make_float4(0.f, 0.f, 0.f, 0.f);                              \
        if (srow >= 0) fst[i] = *(const float4*)(data + srow * CIN + c);       \
    }

#define STS_A(S)                                                               \
    _Pragma("unroll")                                                          \
    for (int i = 0; i < 4; ++i) {                                              \
        int idx = tid + 256 * i;                                               \
        int r = idx >> 4, g = idx & 15;                                        \
        __half2 h01 = __floats2half2_rn(fst[i].x, fst[i].y);                   \
        __half2 h23 = __floats2half2_rn(fst[i].z, fst[i].w);                   \
        *(uint2*)&pool[O_A(S) + r * SA + 2 * g] =                              \
            make_uint2(*reinterpret_cast<unsigned*>(&h01),                     \
                       *reinterpret_cast<unsigned*>(&h23));                    \
    }

#define COPY_B_ASYNC(T, S)                                                     \
    _Pragma("unroll")                                                          \
    for (int i = 0; i < 6; ++i) {                                              \
        int idx = tid + 256 * i;                                               \
        int n = idx >> 3, wg = idx & 7;                                        \
        unsigned dst = sbase + ((unsigned)(O_B(S) + n * SA + 4 * wg) << 2);    \
        CP_ASYNC16(dst, (const void*)&g_wf[(T) * 6144 + n * 32 + 4 * wg]);     \
    }                                                                          \
    CP_COMMIT()

    // Prologue: stage chunk 0
    GATHER(0);
    COPY_B_ASYNC(0, 0);
    STS_A(0);
    CP_WAIT0();
    __syncthreads();

    float acc[2][6][4];
#pragma unroll
    for (int p = 0; p < 2; ++p)
#pragma unroll
        for (int j = 0; j < 6; ++j)
#pragma unroll
            for (int q = 0; q < 4; ++q) acc[p][j][q] = 0.0f;

    for (int t = 0; t < NCHUNK; ++t) {
        const int s = t & 1;
        if (t + 1 < NCHUNK) {
            GATHER(t + 1);                // LDGs in flight during MMA burst
            COPY_B_ASYNC(t + 1, s ^ 1);   // async B copy behind the MMAs
        }

        const unsigned aS = aLane + (unsigned)(s * NW_A * 4);
        const unsigned bS = bLane + (unsigned)(s * NW_B * 4);

#pragma unroll
        for (int s2 = 0; s2 < 4; ++s2) {
            const unsigned ko = (unsigned)(32 * s2);   // 8 words per k16 step
            unsigned ap0[4], ap1[4], bb[12];
            LDSM4(ap0[0], ap0[1], ap0[2], ap0[3], aS + ko);
            LDSM4(ap1[0], ap1[1], ap1[2], ap1[3], aS + (unsigned)(16 * SA * 4) + ko);
            LDSM4(bb[0], bb[1], bb[2],  bb[3],  bS + ko);
            LDSM4(bb[4], bb[5], bb[6],  bb[7],  bS + (unsigned)(16 * SA * 4) + ko);
            LDSM4(bb[8], bb[9], bb[10], bb[11], bS + (unsigned)(32 * SA * 4) + ko);
#pragma unroll
            for (int j = 0; j < 6; ++j) {
                HMMA(acc[0][j], ap0[0], ap0[1], ap0[2], ap0[3], bb[2*j], bb[2*j+1]);
                HMMA(acc[1][j], ap1[0], ap1[1], ap1[2], ap1[3], bb[2*j], bb[2*j+1]);
            }
        }

        if (t + 1 < NCHUNK) STS_A(s ^ 1);
        CP_WAIT0();
        __syncthreads();
    }

    // ---- Epilogue: bias + output + BN partials ----
    float cs[12], cq[12];
#pragma unroll
    for (int i = 0; i < 12; ++i) { cs[i] = 0.0f; cq[i] = 0.0f; }

#pragma unroll
    for (int j = 0; j < 6; ++j) {
        const int cb = wn * 48 + j * 8 + 2 * tig;
        float b0 = __ldg(&bias[cb]);
        float b1 = __ldg(&bias[cb + 1]);
#pragma unroll
        for (int p = 0; p < 2; ++p) {
            const int rb = m0 + wm * 32 + p * 16 + gid;
            const bool v0 = (rb < M_OUT);
            const bool v1 = (rb + 8 < M_OUT);
            float v00 = acc[p][j][0] + b0, v01 = acc[p][j][1] + b1;
            float v10 = acc[p][j][2] + b0, v11 = acc[p][j][3] + b1;
            if (v0) *(float2*)&out[(long long)rb * COUT + cb] = make_float2(v00, v01);
            if (v1) *(float2*)&out[(long long)(rb + 8) * COUT + cb] = make_float2(v10, v11);
            cs[2*j]   += (v0 ? v00 : 0.0f) + (v1 ? v10 : 0.0f);
            cs[2*j+1] += (v0 ? v01 : 0.0f) + (v1 ? v11 : 0.0f);
            cq[2*j]   += (v0 ? v00 * v00 : 0.0f) + (v1 ? v10 * v10 : 0.0f);
            cq[2*j+1] += (v0 ? v01 * v01 : 0.0f) + (v1 ? v11 * v11 : 0.0f);
        }
    }
#pragma unroll
    for (int k = 4; k <= 16; k <<= 1) {
#pragma unroll
        for (int i = 0; i < 12; ++i) {
            cs[i] += __shfl_xor_sync(0xffffffffu, cs[i], k);
            cq[i] += __shfl_xor_sync(0xffffffffu, cq[i], k);
        }
    }
    if (gid == 0) {
#pragma unroll
        for (int j = 0; j < 6; ++j) {
            int col = wn * 48 + j * 8 + 2 * tig;
            RedS[wm * COUT + col]     = cs[2*j];
            RedS[wm * COUT + col + 1] = cs[2*j+1];
            RedQ[wm * COUT + col]     = cq[2*j];
            RedQ[wm * COUT + col + 1] = cq[2*j+1];
        }
    }
    __syncthreads();
    if (tid < COUT) {
        float s = RedS[tid] + RedS[COUT + tid];
        float q = RedQ[tid] + RedQ[COUT + tid];
        g_psum[tid * NBLKP + bx] = s;
        g_psq[tid * NBLKP + bx]  = q;
    }

    // ---- Last-block-done: final CTA computes BN scale/shift ----
    __threadfence();                      // order partial stores before counter
    __syncthreads();
    if (tid == 0)
        *sFlag = (atomicAdd(&g_ctr, 1u) == (unsigned)(NBLK - 1)) ? 1u : 0u;
    __syncthreads();
    if (*sFlag) {
        __threadfence();                  // acquire: see all partials
        if (tid < COUT) {
            const float4* ps = (const float4*)&g_psum[tid * NBLKP];
            const float4* pq = (const float4*)&g_psq [tid * NBLKP];
            float s0 = 0.f, s1 = 0.f, s2 = 0.f, s3 = 0.f;
            float q0 = 0.f, q1 = 0.f, q2 = 0.f, q3 = 0.f;
            for (int b = 0; b < NBLKP / 4; ++b) {
                float4 a = ps[b], d = pq[b];
                s0 += a.x; s1 += a.y; s2 += a.z; s3 += a.w;
                q0 += d.x; q1 += d.y; q2 += d.z; q3 += d.w;
            }
            float s = (s0 + s1) + (s2 + s3);
            float q = (q0 + q1) + (q2 + q3);
            float mean = s / (float)M_OUT;
            float var  = q / (float)M_OUT - mean * mean;
            float rs   = rsqrtf(var + BN_EPS);
            float sc   = gamma[tid] * rs;
            g_scale[tid] = sc;
            g_shift[tid] = beta[tid] - mean * sc;
        }
    }
}

// ---------------------------------------------------------------------------
// Normalize: in-place affine; scale/shift cached in smem as float4;
// 4 float4 per thread. Each block covers 1024 items — grid divisor 1024.
// ---------------------------------------------------------------------------
#define NVEC (M_OUT * COUT / 4)   // 6,000,000
__global__ __launch_bounds__(256) void norm_kernel(float4* __restrict__ out4)
{
    __shared__ float4 sS4[48], sH4[48];
    if (threadIdx.x < 48) {
        sS4[threadIdx.x] = ((const float4*)g_scale)[threadIdx.x];
        sH4[threadIdx.x] = ((const float4*)g_shift)[threadIdx.x];
    }
    __syncthreads();

    int i0 = blockIdx.x * 1024 + threadIdx.x;
#pragma unroll
    for (int u = 0; u < 4; ++u) {
        int i = i0 + u * 256;
        if (i < NVEC) {
            int c4 = i % 48;
            float4 sc = sS4[c4];
            float4 sh = sH4[c4];
            float4 v = out4[i];
            v.x = v.x * sc.x + sh.x;
            v.y = v.y * sc.y + sh.y;
            v.z = v.z * sc.z + sh.z;
            v.w = v.w * sc.w + sh.w;
            out4[i] = v;
        }
    }
}

extern "C" void kernel_launch(void* const* d_in, const int* in_sizes, int n_in,
                              void* d_out, int out_size)
{
    const float* data    = (const float*)d_in[0];
    const float* weights = (const float*)d_in[1];
    const float* bias    = (const float*)d_in[2];
    const float* gamma   = (const float*)d_in[3];
    const float* beta    = (const float*)d_in[4];
    const void*  neigh   = (const void*)d_in[5];
    float* out = (float*)d_out;

    cudaFuncSetAttribute(conv_kernel, cudaFuncAttributeMaxDynamicSharedMemorySize,
                         POOLB);

    prep_kernel<<<NCHUNK + 1, 256>>>(weights, (const int*)neigh);
    conv_kernel<<<NBLK, 256, POOLB>>>(data, bias, gamma, beta, neigh, out);
    norm_kernel<<<(NVEC + 1023) / 1024, 256>>>((float4*)out);
}

// round 15
// speedup vs baseline: 1.4031x; 1.4031x over previous
#include <cuda_runtime.h>
#include <cuda_fp16.h>

// Problem constants
#define M_OUT   125000
#define KNB     8
#define CIN     96
#define COUT    192
#define BM      64
#define NCHUNK  12                        // K chunks of 64 (768 total)
#define NBLK    1954                      // ceil(125000/64)
#define NBLKP   1956                      // padded to /4 for vectorized stats
#define BN_EPS  1e-5f
#define SA      36                        // smem row stride in words (conflict-free)

// Dynamic smem word offsets: A double-buffered, B double-buffered.
#define NW_A    (BM * SA)                 // 2304
#define NW_B    (COUT * SA)               // 6912
#define O_A(s)    ((s) * NW_A)                    // 0 .. 4608
#define O_B(s)    (4608 + (s) * NW_B)             // .. 18432
#define O_SROW    18432                           // 512 words
#define POOLW     18944
#define POOLB     (POOLW * 4)                     // 75776 B -> 2 CTAs/SM

// Deterministic scratch
__device__ float g_psum[COUT * NBLKP];
__device__ float g_psq [COUT * NBLKP];
__device__ __align__(16) float g_scale[COUT];
__device__ __align__(16) float g_shift[COUT];
__device__ int   g_is64;
// Pre-packed fp16 weights: [t][n][w] word = half2 over (k,k+1), k = 64t + 2w
__device__ __align__(16) unsigned g_wf[NCHUNK * COUT * 32];

#define HMMA(d, a0, a1, a2, a3, b0, b1)                                        \
    asm volatile(                                                              \
        "mma.sync.aligned.m16n8k16.row.col.f32.f16.f16.f32 "                   \
        "{%0,%1,%2,%3}, {%4,%5,%6,%7}, {%8,%9}, {%0,%1,%2,%3};"                \
        : "+f"((d)[0]), "+f"((d)[1]), "+f"((d)[2]), "+f"((d)[3])               \
        : "r"(a0), "r"(a1), "r"(a2), "r"(a3), "r"(b0), "r"(b1))

#define LDSM4(r0, r1, r2, r3, addr)                                            \
    asm volatile("ldmatrix.sync.aligned.m8n8.x4.shared.b16 {%0,%1,%2,%3}, [%4];" \
        : "=r"(r0), "=r"(r1), "=r"(r2), "=r"(r3) : "r"(addr))

#define CP_ASYNC16(dst_u32, src_ptr)                                           \
    asm volatile("cp.async.ca.shared.global [%0], [%1], 16;"                   \
        :: "r"(dst_u32), "l"(src_ptr))
#define CP_COMMIT()  asm volatile("cp.async.commit_group;" ::: "memory")
#define CP_WAIT0()   asm volatile("cp.async.wait_group 0;" ::: "memory")

// ---------------------------------------------------------------------------
// Prepack spread over 48 blocks (1536 words each) + aux block 48:
// pad-zero and parallel neigh dtype detect.
// ---------------------------------------------------------------------------
__global__ __launch_bounds__(256) void prep_kernel(const float* __restrict__ W,
                                                   const int* __restrict__ neigh32)
{
    const int bx = blockIdx.x;
    if (bx < 48) {
#pragma unroll
        for (int i = 0; i < 6; ++i) {
            int gidx = bx * 1536 + i * 256 + threadIdx.x;
            int t = gidx / 6144;
            int r = gidx - t * 6144;
            int n = r >> 5, w = r & 31;
            int k0 = t * 64 + 2 * w;
            __half2 h = __floats2half2_rn(W[k0 * COUT + n], W[(k0 + 1) * COUT + n]);
            g_wf[gidx] = *reinterpret_cast<unsigned*>(&h);
        }
    } else {
        // zero the two padded partial slots per channel
        for (int idx = threadIdx.x; idx < COUT * 2; idx += 256) {
            int c = idx >> 1, p = idx & 1;
            g_psum[c * NBLKP + NBLK + p] = 0.0f;
            g_psq [c * NBLKP + NBLK + p] = 0.0f;
        }
        // parallel detect: int64 buffer of indices < 2^31 has all odd words 0
        int nonzero = (neigh32[2 * threadIdx.x + 1] != 0) ? 1 : 0;
        int any = __syncthreads_or(nonzero);
        if (threadIdx.x == 0) g_is64 = any ? 0 : 1;
    }
}

// ---------------------------------------------------------------------------
// Conv kernel: gather-GEMM on fp16 tensor cores.
// Block = 64 rows x 192 cols, 8 warps as 2(M) x 4(N); warp tile 32x48.
// 2 CTAs/SM; B staged via cp.async (no RF round-trip), A via LDG+cvt+STS.
// ---------------------------------------------------------------------------
__global__ __launch_bounds__(256, 2) void conv_kernel(
    const float* __restrict__ data,
    const float* __restrict__ bias,
    const void* __restrict__ neigh_raw,
    float* __restrict__ out)
{
    extern __shared__ __align__(16) unsigned pool[];
    int*   sSrow = (int*)&pool[O_SROW];
    float* RedS  = (float*)pool;              // overlay after MMA: [2][192]
    float* RedQ  = RedS + 2 * COUT;

    const int tid = threadIdx.x;
    const int lid = tid & 31;
    const int wid = tid >> 5;                 // 0..7
    const int wm  = wid & 1;                  // 0..1 (M): rows wm*32..+31
    const int wn  = wid >> 1;                 // 0..3 (N): cols wn*48..+47
    const int gid = lid >> 2;                 // 0..7
    const int tig = lid & 3;                  // 0..3
    const int bx  = blockIdx.x;
    const int m0  = bx * BM;

    const int is64 = g_is64;
    const long long* n64 = (const long long*)neigh_raw;
    const int*       n32 = (const int*)neigh_raw;

    // Stage neighbor indices [64][8]
    for (int idx = tid; idx < BM * KNB; idx += 256) {
        int r  = idx >> 3;
        int kk = idx & 7;
        int m  = m0 + r;
        int srow = -1;
        if (m < M_OUT) {
            long long v = is64 ? n64[(long long)m * KNB + kk]
                               : (long long)n32[(long long)m * KNB + kk];
            if (v >= 0) srow = (int)v;
        }
        sSrow[idx] = srow;
    }
    __syncthreads();

    // ldmatrix lane-static addresses (byte offsets into pool)
    const unsigned sbase = (unsigned)__cvta_generic_to_shared(pool);
    const unsigned aLane = sbase +
        (((wm * 32 + (lid & 15)) * SA + ((lid & 16) ? 4u : 0u)) << 2);
    const unsigned bLane = sbase + ((O_B(0) +
        ((wn * 48 + ((lid >> 4) & 1) * 8 + (lid & 7)) * SA +
         ((lid & 8) ? 4u : 0u))) << 2);

    // Gather staging: 1024 float4 items -> 4 per thread. item -> (row, g)
    float4 fst[4];

#define GATHER(T)                                                              \
    _Pragma("unroll")                                                          \
    for (int i = 0; i < 4; ++i) {                                              \
        int idx = tid + 256 * i;                                               \
        int r = idx >> 4, g = idx & 15;                                        \
        int k0 = ((T) << 6) + (g << 2);                                        \
        int kk = k0 / 96, c = k0 - 96 * kk;                                    \
        int srow = sSrow[r * KNB + kk];                                        \
        fst[i] = make_float4(0.f, 0.f, 0.f, 0.f);                              \
        if (srow >= 0) fst[i] = *(const float4*)(data + srow * CIN + c);       \
    }

#define STS_A(S)                                                               \
    _Pragma("unroll")                                                          \
    for (int i = 0; i < 4; ++i) {                                              \
        int idx = tid + 256 * i;                                               \
        int r = idx >> 4, g = idx & 15;                                        \
        __half2 h01 = __floats2half2_rn(fst[i].x, fst[i].y);                   \
        __half2 h23 = __floats2half2_rn(fst[i].z, fst[i].w);                   \
        *(uint2*)&pool[O_A(S) + r * SA + 2 * g] =                              \
            make_uint2(*reinterpret_cast<unsigned*>(&h01),                     \
                       *reinterpret_cast<unsigned*>(&h23));                    \
    }

    // B copy via cp.async: 1536 16B items, 6 per thread, one commit group.
#define COPY_B_ASYNC(T, S)                                                     \
    _Pragma("unroll")                                                          \
    for (int i = 0; i < 6; ++i) {                                              \
        int idx = tid + 256 * i;                                               \
        int n = idx >> 3, wg = idx & 7;                                        \
        unsigned dst = sbase + ((unsigned)(O_B(S) + n * SA + 4 * wg) << 2);    \
        CP_ASYNC16(dst, (const void*)&g_wf[(T) * 6144 + n * 32 + 4 * wg]);     \
    }                                                                          \
    CP_COMMIT()

    // Prologue: stage chunk 0
    GATHER(0);
    COPY_B_ASYNC(0, 0);
    STS_A(0);
    CP_WAIT0();
    __syncthreads();

    float acc[2][6][4];
#pragma unroll
    for (int p = 0; p < 2; ++p)
#pragma unroll
        for (int j = 0; j < 6; ++j)
#pragma unroll
            for (int q = 0; q < 4; ++q) acc[p][j][q] = 0.0f;

    for (int t = 0; t < NCHUNK; ++t) {
        const int s = t & 1;
        if (t + 1 < NCHUNK) {
            GATHER(t + 1);                // LDGs in flight during MMA burst
            COPY_B_ASYNC(t + 1, s ^ 1);   // async B copy behind the MMAs
        }

        const unsigned aS = aLane + (unsigned)(s * NW_A * 4);
        const unsigned bS = bLane + (unsigned)(s * NW_B * 4);

        // MMA burst over 4 k16 steps of this K64 chunk
#pragma unroll
        for (int s2 = 0; s2 < 4; ++s2) {
            const unsigned ko = (unsigned)(32 * s2);   // 8 words per k16 step
            unsigned ap0[4], ap1[4], bb[12];
            LDSM4(ap0[0], ap0[1], ap0[2], ap0[3], aS + ko);
            LDSM4(ap1[0], ap1[1], ap1[2], ap1[3], aS + (unsigned)(16 * SA * 4) + ko);
            LDSM4(bb[0], bb[1], bb[2],  bb[3],  bS + ko);
            LDSM4(bb[4], bb[5], bb[6],  bb[7],  bS + (unsigned)(16 * SA * 4) + ko);
            LDSM4(bb[8], bb[9], bb[10], bb[11], bS + (unsigned)(32 * SA * 4) + ko);
#pragma unroll
            for (int j = 0; j < 6; ++j) {
                HMMA(acc[0][j], ap0[0], ap0[1], ap0[2], ap0[3], bb[2*j], bb[2*j+1]);
                HMMA(acc[1][j], ap1[0], ap1[1], ap1[2], ap1[3], bb[2*j], bb[2*j+1]);
            }
        }

        if (t + 1 < NCHUNK) STS_A(s ^ 1);
        CP_WAIT0();
        __syncthreads();
    }

    // ---- Epilogue: bias + output + BN partials ----
    float cs[12], cq[12];
#pragma unroll
    for (int i = 0; i < 12; ++i) { cs[i] = 0.0f; cq[i] = 0.0f; }

#pragma unroll
    for (int j = 0; j < 6; ++j) {
        const int cb = wn * 48 + j * 8 + 2 * tig;
        float b0 = __ldg(&bias[cb]);
        float b1 = __ldg(&bias[cb + 1]);
#pragma unroll
        for (int p = 0; p < 2; ++p) {
            const int rb = m0 + wm * 32 + p * 16 + gid;
            const bool v0 = (rb < M_OUT);
            const bool v1 = (rb + 8 < M_OUT);
            float v00 = acc[p][j][0] + b0, v01 = acc[p][j][1] + b1;
            float v10 = acc[p][j][2] + b0, v11 = acc[p][j][3] + b1;
            if (v0) *(float2*)&out[(long long)rb * COUT + cb] = make_float2(v00, v01);
            if (v1) *(float2*)&out[(long long)(rb + 8) * COUT + cb] = make_float2(v10, v11);
            cs[2*j]   += (v0 ? v00 : 0.0f) + (v1 ? v10 : 0.0f);
            cs[2*j+1] += (v0 ? v01 : 0.0f) + (v1 ? v11 : 0.0f);
            cq[2*j]   += (v0 ? v00 * v00 : 0.0f) + (v1 ? v10 * v10 : 0.0f);
            cq[2*j+1] += (v0 ? v01 * v01 : 0.0f) + (v1 ? v11 * v11 : 0.0f);
        }
    }
    // reduce across gid (lane bits 2,3,4)
#pragma unroll
    for (int k = 4; k <= 16; k <<= 1) {
#pragma unroll
        for (int i = 0; i < 12; ++i) {
            cs[i] += __shfl_xor_sync(0xffffffffu, cs[i], k);
            cq[i] += __shfl_xor_sync(0xffffffffu, cq[i], k);
        }
    }
    if (gid == 0) {
#pragma unroll
        for (int j = 0; j < 6; ++j) {
            int col = wn * 48 + j * 8 + 2 * tig;
            RedS[wm * COUT + col]     = cs[2*j];
            RedS[wm * COUT + col + 1] = cs[2*j+1];
            RedQ[wm * COUT + col]     = cq[2*j];
            RedQ[wm * COUT + col + 1] = cq[2*j+1];
        }
    }
    __syncthreads();
    if (tid < COUT) {
        float s = RedS[tid] + RedS[COUT + tid];
        float q = RedQ[tid] + RedQ[COUT + tid];
        g_psum[tid * NBLKP + bx] = s;
        g_psq[tid * NBLKP + bx]  = q;
    }
}

// ---------------------------------------------------------------------------
// Stats: float4-vectorized reduce of 1956 padded partials per channel.
// ---------------------------------------------------------------------------
__global__ __launch_bounds__(256) void stats_kernel(
    const float* __restrict__ gamma,
    const float* __restrict__ beta)
{
    const int c = blockIdx.x;
    const int t = threadIdx.x;
    const float4* ps = (const float4*)&g_psum[c * NBLKP];
    const float4* pq = (const float4*)&g_psq [c * NBLKP];
    float s = 0.0f, q = 0.0f;
    for (int b = t; b < NBLKP / 4; b += 256) {
        float4 a = ps[b], d = pq[b];
        s += (a.x + a.y) + (a.z + a.w);
        q += (d.x + d.y) + (d.z + d.w);
    }
    __shared__ float ss[256], sq[256];
    ss[t] = s; sq[t] = q;
    __syncthreads();
    for (int o = 128; o > 0; o >>= 1) {
        if (t < o) { ss[t] += ss[t + o]; sq[t] += sq[t + o]; }
        __syncthreads();
    }
    if (t == 0) {
        float mean = ss[0] / (float)M_OUT;
        float var  = sq[0] / (float)M_OUT - mean * mean;
        float rs   = rsqrtf(var + BN_EPS);
        float sc   = gamma[c] * rs;
        g_scale[c] = sc;
        g_shift[c] = beta[c] - mean * sc;
    }
}

// ---------------------------------------------------------------------------
// Normalize: in-place affine; scale/shift cached in smem as float4;
// 4 float4 per thread. Each block covers 1024 items — grid divisor 1024.
// ---------------------------------------------------------------------------
#define NVEC (M_OUT * COUT / 4)   // 6,000,000
__global__ __launch_bounds__(256) void norm_kernel(float4* __restrict__ out4)
{
    __shared__ float4 sS4[48], sH4[48];
    if (threadIdx.x < 48) {
        sS4[threadIdx.x] = ((const float4*)g_scale)[threadIdx.x];
        sH4[threadIdx.x] = ((const float4*)g_shift)[threadIdx.x];
    }
    __syncthreads();

    int i0 = blockIdx.x * 1024 + threadIdx.x;
#pragma unroll
    for (int u = 0; u < 4; ++u) {
        int i = i0 + u * 256;
        if (i < NVEC) {
            int c4 = i % 48;
            float4 sc = sS4[c4];
            float4 sh = sH4[c4];
            float4 v = out4[i];
            v.x = v.x * sc.x + sh.x;
            v.y = v.y * sc.y + sh.y;
            v.z = v.z * sc.z + sh.z;
            v.w = v.w * sc.w + sh.w;
            out4[i] = v;
        }
    }
}

extern "C" void kernel_launch(void* const* d_in, const int* in_sizes, int n_in,
                              void* d_out, int out_size)
{
    const float* data    = (const float*)d_in[0];
    const float* weights = (const float*)d_in[1];
    const float* bias    = (const float*)d_in[2];
    const float* gamma   = (const float*)d_in[3];
    const float* beta    = (const float*)d_in[4];
    const void*  neigh   = (const void*)d_in[5];
    float* out = (float*)d_out;

    cudaFuncSetAttribute(conv_kernel, cudaFuncAttributeMaxDynamicSharedMemorySize,
                         POOLB);

    prep_kernel<<<49, 256>>>(weights, (const int*)neigh);
    conv_kernel<<<NBLK, 256, POOLB>>>(data, bias, neigh, out);
    stats_kernel<<<COUT, 256>>>(gamma, beta);
    norm_kernel<<<(NVEC + 1023) / 1024, 256>>>((float4*)out);
}

// round 16
// speedup vs baseline: 1.4144x; 1.0080x over previous
#include <cuda_runtime.h>
#include <cuda_fp16.h>

// Problem constants
#define M_OUT   125000
#define KNB     8
#define CIN     96
#define COUT    192
#define BM      64
#define NCHUNK  12                        // K chunks of 64 (768 total)
#define NBLK    1954                      // ceil(125000/64)
#define NBLKP   1956                      // padded to /4 for vectorized stats
#define BN_EPS  1e-5f
#define SA      36                        // smem row stride in words (conflict-free)

// Dynamic smem word offsets: A double-buffered, B double-buffered.
#define NW_A    (BM * SA)                 // 2304
#define NW_B    (COUT * SA)               // 6912
#define O_A(s)    ((s) * NW_A)                    // 0 .. 4608
#define O_B(s)    (4608 + (s) * NW_B)             // .. 18432
#define O_SROW    18432                           // 512 words
#define POOLW     18944
#define POOLB     (POOLW * 4)                     // 75776 B -> 2 CTAs/SM

// Deterministic scratch
__device__ float g_psum[COUT * NBLKP];
__device__ float g_psq [COUT * NBLKP];
__device__ __align__(16) float g_scale[COUT];
__device__ __align__(16) float g_shift[COUT];
__device__ int   g_is64;
// Pre-packed fp16 weights: [t][n][w] word = half2 over (k,k+1), k = 64t + 2w
__device__ __align__(16) unsigned g_wf[NCHUNK * COUT * 32];

#define HMMA(d, a0, a1, a2, a3, b0, b1)                                        \
    asm volatile(                                                              \
        "mma.sync.aligned.m16n8k16.row.col.f32.f16.f16.f32 "                   \
        "{%0,%1,%2,%3}, {%4,%5,%6,%7}, {%8,%9}, {%0,%1,%2,%3};"                \
        : "+f"((d)[0]), "+f"((d)[1]), "+f"((d)[2]), "+f"((d)[3])               \
        : "r"(a0), "r"(a1), "r"(a2), "r"(a3), "r"(b0), "r"(b1))

#define LDSM4(r0, r1, r2, r3, addr)                                            \
    asm volatile("ldmatrix.sync.aligned.m8n8.x4.shared.b16 {%0,%1,%2,%3}, [%4];" \
        : "=r"(r0), "=r"(r1), "=r"(r2), "=r"(r3) : "r"(addr))

#define CP_ASYNC16(dst_u32, src_ptr)                                           \
    asm volatile("cp.async.ca.shared.global [%0], [%1], 16;"                   \
        :: "r"(dst_u32), "l"(src_ptr))
#define CP_COMMIT()  asm volatile("cp.async.commit_group;" ::: "memory")
#define CP_WAIT0()   asm volatile("cp.async.wait_group 0;" ::: "memory")

// ---------------------------------------------------------------------------
// Prepack spread over 48 blocks (1536 words each) + aux block 48:
// pad-zero and parallel neigh dtype detect.
// ---------------------------------------------------------------------------
__global__ __launch_bounds__(256) void prep_kernel(const float* __restrict__ W,
                                                   const int* __restrict__ neigh32)
{
    const int bx = blockIdx.x;
    if (bx < 48) {
#pragma unroll
        for (int i = 0; i < 6; ++i) {
            int gidx = bx * 1536 + i * 256 + threadIdx.x;
            int t = gidx / 6144;
            int r = gidx - t * 6144;
            int n = r >> 5, w = r & 31;
            int k0 = t * 64 + 2 * w;
            __half2 h = __floats2half2_rn(W[k0 * COUT + n], W[(k0 + 1) * COUT + n]);
            g_wf[gidx] = *reinterpret_cast<unsigned*>(&h);
        }
    } else {
        // zero the two padded partial slots per channel
        for (int idx = threadIdx.x; idx < COUT * 2; idx += 256) {
            int c = idx >> 1, p = idx & 1;
            g_psum[c * NBLKP + NBLK + p] = 0.0f;
            g_psq [c * NBLKP + NBLK + p] = 0.0f;
        }
        // parallel detect: int64 buffer of indices < 2^31 has all odd words 0
        int nonzero = (neigh32[2 * threadIdx.x + 1] != 0) ? 1 : 0;
        int any = __syncthreads_or(nonzero);
        if (threadIdx.x == 0) g_is64 = any ? 0 : 1;
    }
}

// ---------------------------------------------------------------------------
// Conv kernel: gather-GEMM on fp16 tensor cores.
// Block = 64 rows x 192 cols, 8 warps as 2(M) x 4(N); warp tile 32x48.
// 2 CTAs/SM; B staged via cp.async (no RF round-trip), A via LDG+cvt+STS.
// ---------------------------------------------------------------------------
__global__ __launch_bounds__(256, 2) void conv_kernel(
    const float* __restrict__ data,
    const float* __restrict__ bias,
    const void* __restrict__ neigh_raw,
    float* __restrict__ out)
{
    extern __shared__ __align__(16) unsigned pool[];
    int*   sSrow = (int*)&pool[O_SROW];
    float* RedS  = (float*)pool;              // overlay after MMA: [2][192]
    float* RedQ  = RedS + 2 * COUT;

    const int tid = threadIdx.x;
    const int lid = tid & 31;
    const int wid = tid >> 5;                 // 0..7
    const int wm  = wid & 1;                  // 0..1 (M): rows wm*32..+31
    const int wn  = wid >> 1;                 // 0..3 (N): cols wn*48..+47
    const int gid = lid >> 2;                 // 0..7
    const int tig = lid & 3;                  // 0..3
    const int bx  = blockIdx.x;
    const int m0  = bx * BM;

    const int is64 = g_is64;
    const long long* n64 = (const long long*)neigh_raw;
    const int*       n32 = (const int*)neigh_raw;

    // Stage neighbor indices [64][8]
    for (int idx = tid; idx < BM * KNB; idx += 256) {
        int r  = idx >> 3;
        int kk = idx & 7;
        int m  = m0 + r;
        int srow = -1;
        if (m < M_OUT) {
            long long v = is64 ? n64[(long long)m * KNB + kk]
                               : (long long)n32[(long long)m * KNB + kk];
            if (v >= 0) srow = (int)v;
        }
        sSrow[idx] = srow;
    }
    __syncthreads();

    // ldmatrix lane-static addresses (byte offsets into pool)
    const unsigned sbase = (unsigned)__cvta_generic_to_shared(pool);
    const unsigned aLane = sbase +
        (((wm * 32 + (lid & 15)) * SA + ((lid & 16) ? 4u : 0u)) << 2);
    const unsigned bLane = sbase + ((O_B(0) +
        ((wn * 48 + ((lid >> 4) & 1) * 8 + (lid & 7)) * SA +
         ((lid & 8) ? 4u : 0u))) << 2);

    // Gather staging: 1024 float4 items -> 4 per thread. item -> (row, g)
    float4 fst[4];

#define GATHER(T)                                                              \
    _Pragma("unroll")                                                          \
    for (int i = 0; i < 4; ++i) {                                              \
        int idx = tid + 256 * i;                                               \
        int r = idx >> 4, g = idx & 15;                                        \
        int k0 = ((T) << 6) + (g << 2);                                        \
        int kk = k0 / 96, c = k0 - 96 * kk;                                    \
        int srow = sSrow[r * KNB + kk];                                        \
        fst[i] = make_float4(0.f, 0.f, 0.f, 0.f);                              \
        if (srow >= 0) fst[i] = *(const float4*)(data + srow * CIN + c);       \
    }

#define STS_A(S)                                                               \
    _Pragma("unroll")                                                          \
    for (int i = 0; i < 4; ++i) {                                              \
        int idx = tid + 256 * i;                                               \
        int r = idx >> 4, g = idx & 15;                                        \
        __half2 h01 = __floats2half2_rn(fst[i].x, fst[i].y);                   \
        __half2 h23 = __floats2half2_rn(fst[i].z, fst[i].w);                   \
        *(uint2*)&pool[O_A(S) + r * SA + 2 * g] =                              \
            make_uint2(*reinterpret_cast<unsigned*>(&h01),                     \
                       *reinterpret_cast<unsigned*>(&h23));                    \
    }

    // B copy via cp.async: 1536 16B items, 6 per thread, one commit group.
#define COPY_B_ASYNC(T, S)                                                     \
    _Pragma("unroll")                                                          \
    for (int i = 0; i < 6; ++i) {                                              \
        int idx = tid + 256 * i;                                               \
        int n = idx >> 3, wg = idx & 7;                                        \
        unsigned dst = sbase + ((unsigned)(O_B(S) + n * SA + 4 * wg) << 2);    \
        CP_ASYNC16(dst, (const void*)&g_wf[(T) * 6144 + n * 32 + 4 * wg]);     \
    }                                                                          \
    CP_COMMIT()

    // Prologue: stage chunk 0
    GATHER(0);
    COPY_B_ASYNC(0, 0);
    STS_A(0);
    CP_WAIT0();
    __syncthreads();

    float acc[2][6][4];
#pragma unroll
    for (int p = 0; p < 2; ++p)
#pragma unroll
        for (int j = 0; j < 6; ++j)
#pragma unroll
            for (int q = 0; q < 4; ++q) acc[p][j][q] = 0.0f;

    for (int t = 0; t < NCHUNK; ++t) {
        const int s = t & 1;
        if (t + 1 < NCHUNK) {
            GATHER(t + 1);                // LDGs in flight during MMA burst
            COPY_B_ASYNC(t + 1, s ^ 1);   // async B copy behind the MMAs
        }

        const unsigned aS = aLane + (unsigned)(s * NW_A * 4);
        const unsigned bS = bLane + (unsigned)(s * NW_B * 4);

        // MMA burst over 4 k16 steps of this K64 chunk
#pragma unroll
        for (int s2 = 0; s2 < 4; ++s2) {
            const unsigned ko = (unsigned)(32 * s2);   // 8 words per k16 step
            unsigned ap0[4], ap1[4], bb[12];
            LDSM4(ap0[0], ap0[1], ap0[2], ap0[3], aS + ko);
            LDSM4(ap1[0], ap1[1], ap1[2], ap1[3], aS + (unsigned)(16 * SA * 4) + ko);
            LDSM4(bb[0], bb[1], bb[2],  bb[3],  bS + ko);
            LDSM4(bb[4], bb[5], bb[6],  bb[7],  bS + (unsigned)(16 * SA * 4) + ko);
            LDSM4(bb[8], bb[9], bb[10], bb[11], bS + (unsigned)(32 * SA * 4) + ko);
#pragma unroll
            for (int j = 0; j < 6; ++j) {
                HMMA(acc[0][j], ap0[0], ap0[1], ap0[2], ap0[3], bb[2*j], bb[2*j+1]);
                HMMA(acc[1][j], ap1[0], ap1[1], ap1[2], ap1[3], bb[2*j], bb[2*j+1]);
            }
        }

        if (t + 1 < NCHUNK) STS_A(s ^ 1);
        CP_WAIT0();
        __syncthreads();
    }

    // ---- Epilogue: bias + output + BN partials ----
    float cs[12], cq[12];
#pragma unroll
    for (int i = 0; i < 12; ++i) { cs[i] = 0.0f; cq[i] = 0.0f; }

#pragma unroll
    for (int j = 0; j < 6; ++j) {
        const int cb = wn * 48 + j * 8 + 2 * tig;
        float b0 = __ldg(&bias[cb]);
        float b1 = __ldg(&bias[cb + 1]);
#pragma unroll
        for (int p = 0; p < 2; ++p) {
            const int rb = m0 + wm * 32 + p * 16 + gid;
            const bool v0 = (rb < M_OUT);
            const bool v1 = (rb + 8 < M_OUT);
            float v00 = acc[p][j][0] + b0, v01 = acc[p][j][1] + b1;
            float v10 = acc[p][j][2] + b0, v11 = acc[p][j][3] + b1;
            if (v0) *(float2*)&out[(long long)rb * COUT + cb] = make_float2(v00, v01);
            if (v1) *(float2*)&out[(long long)(rb + 8) * COUT + cb] = make_float2(v10, v11);
            cs[2*j]   += (v0 ? v00 : 0.0f) + (v1 ? v10 : 0.0f);
            cs[2*j+1] += (v0 ? v01 : 0.0f) + (v1 ? v11 : 0.0f);
            cq[2*j]   += (v0 ? v00 * v00 : 0.0f) + (v1 ? v10 * v10 : 0.0f);
            cq[2*j+1] += (v0 ? v01 * v01 : 0.0f) + (v1 ? v11 * v11 : 0.0f);
        }
    }
    // reduce across gid (lane bits 2,3,4)
#pragma unroll
    for (int k = 4; k <= 16; k <<= 1) {
#pragma unroll
        for (int i = 0; i < 12; ++i) {
            cs[i] += __shfl_xor_sync(0xffffffffu, cs[i], k);
            cq[i] += __shfl_xor_sync(0xffffffffu, cq[i], k);
        }
    }
    if (gid == 0) {
#pragma unroll
        for (int j = 0; j < 6; ++j) {
            int col = wn * 48 + j * 8 + 2 * tig;
            RedS[wm * COUT + col]     = cs[2*j];
            RedS[wm * COUT + col + 1] = cs[2*j+1];
            RedQ[wm * COUT + col]     = cq[2*j];
            RedQ[wm * COUT + col + 1] = cq[2*j+1];
        }
    }
    __syncthreads();
    if (tid < COUT) {
        float s = RedS[tid] + RedS[COUT + tid];
        float q = RedQ[tid] + RedQ[COUT + tid];
        g_psum[tid * NBLKP + bx] = s;
        g_psq[tid * NBLKP + bx]  = q;
    }
}

// ---------------------------------------------------------------------------
// Stats: float4-vectorized reduce of 1956 padded partials per channel.
// ---------------------------------------------------------------------------
__global__ __launch_bounds__(256) void stats_kernel(
    const float* __restrict__ gamma,
    const float* __restrict__ beta)
{
    const int c = blockIdx.x;
    const int t = threadIdx.x;
    const float4* ps = (const float4*)&g_psum[c * NBLKP];
    const float4* pq = (const float4*)&g_psq [c * NBLKP];
    float s = 0.0f, q = 0.0f;
    for (int b = t; b < NBLKP / 4; b += 256) {
        float4 a = ps[b], d = pq[b];
        s += (a.x + a.y) + (a.z + a.w);
        q += (d.x + d.y) + (d.z + d.w);
    }
    __shared__ float ss[256], sq[256];
    ss[t] = s; sq[t] = q;
    __syncthreads();
    for (int o = 128; o > 0; o >>= 1) {
        if (t < o) { ss[t] += ss[t + o]; sq[t] += sq[t + o]; }
        __syncthreads();
    }
    if (t == 0) {
        float mean = ss[0] / (float)M_OUT;
        float var  = sq[0] / (float)M_OUT - mean * mean;
        float rs   = rsqrtf(var + BN_EPS);
        float sc   = gamma[c] * rs;
        g_scale[c] = sc;
        g_shift[c] = beta[c] - mean * sc;
    }
}

// ---------------------------------------------------------------------------
// Normalize: in-place affine; scale/shift cached in smem as float4.
// 8 float4 per thread; block b covers items [b*2048, b*2048+2048).
// Blocks run in REVERSE order of conv's write order so the earliest norm
// blocks hit the freshest (still L2-resident) conv output lines.
// ---------------------------------------------------------------------------
#define NVEC (M_OUT * COUT / 4)   // 6,000,000
__global__ __launch_bounds__(256) void norm_kernel(float4* __restrict__ out4)
{
    __shared__ float4 sS4[48], sH4[48];
    if (threadIdx.x < 48) {
        sS4[threadIdx.x] = ((const float4*)g_scale)[threadIdx.x];
        sH4[threadIdx.x] = ((const float4*)g_shift)[threadIdx.x];
    }
    __syncthreads();

    const int b = gridDim.x - 1 - blockIdx.x;      // reverse traversal
    int i0 = b * 2048 + threadIdx.x;
#pragma unroll
    for (int u = 0; u < 8; ++u) {
        int i = i0 + u * 256;
        if (i < NVEC) {
            int c4 = i % 48;
            float4 sc = sS4[c4];
            float4 sh = sH4[c4];
            float4 v = out4[i];
            v.x = v.x * sc.x + sh.x;
            v.y = v.y * sc.y + sh.y;
            v.z = v.z * sc.z + sh.z;
            v.w = v.w * sc.w + sh.w;
            out4[i] = v;
        }
    }
}

extern "C" void kernel_launch(void* const* d_in, const int* in_sizes, int n_in,
                              void* d_out, int out_size)
{
    const float* data    = (const float*)d_in[0];
    const float* weights = (const float*)d_in[1];
    const float* bias    = (const float*)d_in[2];
    const float* gamma   = (const float*)d_in[3];
    const float* beta    = (const float*)d_in[4];
    const void*  neigh   = (const void*)d_in[5];
    float* out = (float*)d_out;

    cudaFuncSetAttribute(conv_kernel, cudaFuncAttributeMaxDynamicSharedMemorySize,
                         POOLB);

    prep_kernel<<<49, 256>>>(weights, (const int*)neigh);
    conv_kernel<<<NBLK, 256, POOLB>>>(data, bias, neigh, out);
    stats_kernel<<<COUT, 256>>>(gamma, beta);
    norm_kernel<<<(NVEC + 2047) / 2048, 256>>>((float4*)out);
}